// round 1
// baseline (speedup 1.0000x reference)
#include <cuda_runtime.h>
#include <math.h>

// Problem constants (fixed by the reference)
#define NB   8192          // batch
#define NC   200           // classes
#define NK   16            // components per class
#define ND   512           // feature dim
#define NCK  3200          // NC*NK
#define K2   1024          // 2*ND (concatenated GEMM K)

#define D_LOG_2PI 940.9930579935848f   // 512 * log(2*pi)

// ---------------- scratch (device globals; no allocations) ----------------
__device__ float g_A[NB * K2];        // [x^2 | x]            32 MB
__device__ float g_Bm[NCK * K2];      // [invb | -2*mu*invb]  13 MB
__device__ float g_bias[NCK];         // -0.5*(DLOG2PI+logdet+c_j) + logw_j
__device__ float g_logw[NCK];
__device__ float g_logp[NC];
__device__ float g_comp[NB * NCK];    // per-component log prob, 105 MB

// ---------------- prep: A' = [x^2, x] ----------------
__global__ void prep_x_kernel(const float* __restrict__ x) {
    int i = blockIdx.x * blockDim.x + threadIdx.x;   // over NB*ND
    if (i < NB * ND) {
        int b = i / ND;
        int d = i - b * ND;
        float v = x[i];
        g_A[b * K2 + d]      = v * v;
        g_A[b * K2 + ND + d] = v;
    }
}

// ---------------- prep: weight softmax (per class) + prior softmax ----------------
__global__ void prep_wp_kernel(const float* __restrict__ weights,
                               const float* __restrict__ priors) {
    __shared__ float sh[256];
    int t = threadIdx.x;

    // per-class softmax over K=16 weights -> log(w + 1e-6)
    if (t < NC) {
        float wv[NK];
        float m = -1e30f;
        #pragma unroll
        for (int k = 0; k < NK; k++) {
            wv[k] = weights[t * NK + k];
            m = fmaxf(m, wv[k]);
        }
        float s = 0.f;
        #pragma unroll
        for (int k = 0; k < NK; k++) s += expf(wv[k] - m);
        float inv_s = 1.f / s;
        #pragma unroll
        for (int k = 0; k < NK; k++)
            g_logw[t * NK + k] = logf(expf(wv[k] - m) * inv_s + 1e-6f);
    }

    // prior softmax over C=200 -> log(p + 1e-6)
    float pv = (t < NC) ? priors[t] : -1e30f;
    sh[t] = pv;
    __syncthreads();
    for (int s = 128; s > 0; s >>= 1) {
        if (t < s) sh[t] = fmaxf(sh[t], sh[t + s]);
        __syncthreads();
    }
    float M = sh[0];
    __syncthreads();
    float e = (t < NC) ? expf(pv - M) : 0.f;
    sh[t] = e;
    __syncthreads();
    for (int s = 128; s > 0; s >>= 1) {
        if (t < s) sh[t] += sh[t + s];
        __syncthreads();
    }
    float S = sh[0];
    if (t < NC) g_logp[t] = logf(e / S + 1e-6f);
}

// ---------------- prep: B' = [invb, -2*mu*invb], bias_j ----------------
__global__ void prep_comp_kernel(const float* __restrict__ means,
                                 const float* __restrict__ bw) {
    int j = blockIdx.x;      // component
    int t = threadIdx.x;     // 128 threads
    float ld = 0.f, cj = 0.f;
    #pragma unroll
    for (int d = t; d < ND; d += 128) {
        float bv = bw[j * ND + d];
        bv = fminf(fmaxf(bv, 1e-6f), 1000.f);
        float inv = 1.0f / bv;
        float mu  = means[j * ND + d];
        g_Bm[j * K2 + d]      = inv;
        g_Bm[j * K2 + ND + d] = -2.0f * mu * inv;
        ld += logf(bv);
        cj += mu * mu * inv;
    }
    // block reduce (128 threads = 4 warps)
    __shared__ float shd[128], shc[128];
    shd[t] = ld; shc[t] = cj;
    __syncthreads();
    for (int s = 64; s > 0; s >>= 1) {
        if (t < s) { shd[t] += shd[t + s]; shc[t] += shc[t + s]; }
        __syncthreads();
    }
    if (t == 0)
        g_bias[j] = -0.5f * (D_LOG_2PI + shd[0] + shc[0]) + g_logw[j];
}

// ---------------- main GEMM: g_comp = -0.5 * (A' @ B'^T) + bias ----------------
#define BM 128
#define BN 128
#define BK 16

__global__ void __launch_bounds__(256, 2) gemm_kernel() {
    __shared__ float As[BK][BM];
    __shared__ float Bs[BK][BN];

    int t  = threadIdx.x;
    int tx = t & 15;         // N direction
    int ty = t >> 4;         // M direction
    int rowBase = blockIdx.y * BM;
    int colBase = blockIdx.x * BN;

    int lrow = t >> 2;       // 0..63
    int lcg  = t & 3;        // 0..3 (float4 group along K)

    float acc[8][8];
    #pragma unroll
    for (int i = 0; i < 8; i++)
        #pragma unroll
        for (int j = 0; j < 8; j++) acc[i][j] = 0.f;

    for (int k0 = 0; k0 < K2; k0 += BK) {
        // load A tile (128x16) and B tile (128x16), transposed into smem
        #pragma unroll
        for (int rr = 0; rr < 2; rr++) {
            int r = lrow + rr * 64;
            float4 va = *(const float4*)&g_A[(size_t)(rowBase + r) * K2 + k0 + lcg * 4];
            As[lcg * 4 + 0][r] = va.x;
            As[lcg * 4 + 1][r] = va.y;
            As[lcg * 4 + 2][r] = va.z;
            As[lcg * 4 + 3][r] = va.w;
            float4 vb = *(const float4*)&g_Bm[(size_t)(colBase + r) * K2 + k0 + lcg * 4];
            Bs[lcg * 4 + 0][r] = vb.x;
            Bs[lcg * 4 + 1][r] = vb.y;
            Bs[lcg * 4 + 2][r] = vb.z;
            Bs[lcg * 4 + 3][r] = vb.w;
        }
        __syncthreads();

        #pragma unroll
        for (int k = 0; k < BK; k++) {
            float4 a0 = *(const float4*)&As[k][ty * 8];
            float4 a1 = *(const float4*)&As[k][ty * 8 + 4];
            float4 b0 = *(const float4*)&Bs[k][tx * 8];
            float4 b1 = *(const float4*)&Bs[k][tx * 8 + 4];
            float a[8] = {a0.x, a0.y, a0.z, a0.w, a1.x, a1.y, a1.z, a1.w};
            float b[8] = {b0.x, b0.y, b0.z, b0.w, b1.x, b1.y, b1.z, b1.w};
            #pragma unroll
            for (int i = 0; i < 8; i++)
                #pragma unroll
                for (int j = 0; j < 8; j++)
                    acc[i][j] = fmaf(a[i], b[j], acc[i][j]);
        }
        __syncthreads();
    }

    // epilogue: -0.5*md + bias -> g_comp
    float4 bias0 = *(const float4*)&g_bias[colBase + tx * 8];
    float4 bias1 = *(const float4*)&g_bias[colBase + tx * 8 + 4];
    #pragma unroll
    for (int i = 0; i < 8; i++) {
        size_t row = (size_t)(rowBase + ty * 8 + i);
        float4 o0, o1;
        o0.x = fmaf(-0.5f, acc[i][0], bias0.x);
        o0.y = fmaf(-0.5f, acc[i][1], bias0.y);
        o0.z = fmaf(-0.5f, acc[i][2], bias0.z);
        o0.w = fmaf(-0.5f, acc[i][3], bias0.w);
        o1.x = fmaf(-0.5f, acc[i][4], bias1.x);
        o1.y = fmaf(-0.5f, acc[i][5], bias1.y);
        o1.z = fmaf(-0.5f, acc[i][6], bias1.z);
        o1.w = fmaf(-0.5f, acc[i][7], bias1.w);
        *(float4*)&g_comp[row * NCK + colBase + tx * 8]     = o0;
        *(float4*)&g_comp[row * NCK + colBase + tx * 8 + 4] = o1;
    }
}

// ---------------- per-row reduction: lse over K, +logp, row normalize ----------------
__global__ void reduce_kernel(float* __restrict__ out) {
    __shared__ float sh[256];
    size_t row = blockIdx.x;
    int t = threadIdx.x;

    float lc = -1e30f;
    if (t < NC) {
        const float4* p = (const float4*)&g_comp[row * NCK + t * NK];
        float4 v0 = p[0], v1 = p[1], v2 = p[2], v3 = p[3];
        float v[NK] = {v0.x, v0.y, v0.z, v0.w, v1.x, v1.y, v1.z, v1.w,
                       v2.x, v2.y, v2.z, v2.w, v3.x, v3.y, v3.z, v3.w};
        float m = v[0];
        #pragma unroll
        for (int k = 1; k < NK; k++) m = fmaxf(m, v[k]);
        float s = 0.f;
        #pragma unroll
        for (int k = 0; k < NK; k++) s += expf(v[k] - m);
        lc = m + logf(s) + g_logp[t];
    }

    sh[t] = lc;
    __syncthreads();
    for (int s = 128; s > 0; s >>= 1) {
        if (t < s) sh[t] = fmaxf(sh[t], sh[t + s]);
        __syncthreads();
    }
    float M = sh[0];
    __syncthreads();
    sh[t] = (t < NC) ? expf(lc - M) : 0.f;
    __syncthreads();
    for (int s = 128; s > 0; s >>= 1) {
        if (t < s) sh[t] += sh[t + s];
        __syncthreads();
    }
    float lse = M + logf(sh[0]);
    if (t < NC) out[row * NC + t] = lc - lse;
}

// ---------------- launch ----------------
extern "C" void kernel_launch(void* const* d_in, const int* in_sizes, int n_in,
                              void* d_out, int out_size) {
    const float* x       = (const float*)d_in[0];   // [8192, 512]
    const float* means   = (const float*)d_in[1];   // [3200, 512]
    const float* bw      = (const float*)d_in[2];   // [3200, 512]
    const float* weights = (const float*)d_in[3];   // [3200]
    const float* priors  = (const float*)d_in[4];   // [200]
    float* out = (float*)d_out;                     // [8192, 200]

    prep_x_kernel<<<(NB * ND + 255) / 256, 256>>>(x);
    prep_wp_kernel<<<1, 256>>>(weights, priors);
    prep_comp_kernel<<<NCK, 128>>>(means, bw);

    dim3 grid(NCK / BN, NB / BM);   // (25, 64)
    gemm_kernel<<<grid, 256>>>();

    reduce_kernel<<<NB, 256>>>(out);
}

// round 3
// speedup vs baseline: 2.4297x; 2.4297x over previous
#include <cuda_runtime.h>
#include <cuda_bf16.h>
#include <math.h>
#include <stdint.h>

// Problem constants
#define NB   8192
#define NC   200
#define NK   16
#define ND   512
#define NCK  3200
#define K2   1024          // 2*ND concatenated GEMM K
#define D_LOG_2PI 940.9930579935848f

// GEMM tiling
#define BM 256
#define BN 128
#define BK 64              // bf16 per stage row (128 bytes, SW128 atom)
#define NSTEPS (K2/BK)     // 16
#define NTHR 512

// SMEM layout (dynamic):
//  [0:512)    bias_sm (128 floats)
//  [512 + s*STAGE): stage s: Ah(32K) Al(32K) Bh(16K) Bl(16K)
//  epilogue reuses [512, ...) as C staging (256 x 136 floats)
#define STAGE_BYTES 98304
#define SMEM_TOTAL  (512 + 2 * STAGE_BYTES)
#define CPAD 136

// ---------------- scratch (device globals) ----------------
__device__ __nv_bfloat16 g_Ah[NB * K2];
__device__ __nv_bfloat16 g_Al[NB * K2];
__device__ __nv_bfloat16 g_Bh[NCK * K2];
__device__ __nv_bfloat16 g_Bl[NCK * K2];
__device__ float g_bias[NCK];
__device__ float g_logw[NCK];
__device__ float g_logp[NC];
__device__ float g_cls[NB * NC];

// ---------------- helpers ----------------
__device__ __forceinline__ uint32_t smem_u32(const void* p) {
    uint32_t a;
    asm("{ .reg .u64 t; cvta.to.shared.u64 t, %1; cvt.u32.u64 %0, t; }" : "=r"(a) : "l"(p));
    return a;
}
__device__ __forceinline__ uint32_t swz(uint32_t o) {   // SW128, 128B rows
    return o ^ (((o >> 7) & 7) << 4);
}
__device__ __forceinline__ void cp16(uint32_t saddr, const void* gaddr) {
    asm volatile("cp.async.cg.shared.global [%0], [%1], 16;" :: "r"(saddr), "l"(gaddr));
}
__device__ __forceinline__ void ldsm4(uint32_t* r, uint32_t addr) {
    asm volatile("ldmatrix.sync.aligned.m8n8.x4.shared.b16 {%0,%1,%2,%3}, [%4];"
        : "=r"(r[0]), "=r"(r[1]), "=r"(r[2]), "=r"(r[3]) : "r"(addr));
}
__device__ __forceinline__ void mma_bf16(float* c, const uint32_t* a, const uint32_t* b) {
    asm volatile(
        "mma.sync.aligned.m16n8k16.row.col.f32.bf16.bf16.f32 "
        "{%0,%1,%2,%3}, {%4,%5,%6,%7}, {%8,%9}, {%0,%1,%2,%3};"
        : "+f"(c[0]), "+f"(c[1]), "+f"(c[2]), "+f"(c[3])
        : "r"(a[0]), "r"(a[1]), "r"(a[2]), "r"(a[3]), "r"(b[0]), "r"(b[1]));
}

// ---------------- prep kernels ----------------
__global__ void prep_x_kernel(const float* __restrict__ x) {
    int i = blockIdx.x * blockDim.x + threadIdx.x;
    if (i < NB * ND) {
        int b = i >> 9, d = i & 511;
        float v = x[i];
        float a = v * v;
        __nv_bfloat16 h = __float2bfloat16(a);
        g_Ah[b * K2 + d] = h;
        g_Al[b * K2 + d] = __float2bfloat16(a - __bfloat162float(h));
        __nv_bfloat16 h2 = __float2bfloat16(v);
        g_Ah[b * K2 + ND + d] = h2;
        g_Al[b * K2 + ND + d] = __float2bfloat16(v - __bfloat162float(h2));
    }
}

__global__ void prep_wp_kernel(const float* __restrict__ weights,
                               const float* __restrict__ priors) {
    __shared__ float sh[256];
    int t = threadIdx.x;
    if (t < NC) {
        float wv[NK];
        float m = -1e30f;
        #pragma unroll
        for (int k = 0; k < NK; k++) { wv[k] = weights[t * NK + k]; m = fmaxf(m, wv[k]); }
        float s = 0.f;
        #pragma unroll
        for (int k = 0; k < NK; k++) s += expf(wv[k] - m);
        float inv_s = 1.f / s;
        #pragma unroll
        for (int k = 0; k < NK; k++)
            g_logw[t * NK + k] = logf(expf(wv[k] - m) * inv_s + 1e-6f);
    }
    float pv = (t < NC) ? priors[t] : -1e30f;
    sh[t] = pv;
    __syncthreads();
    for (int s = 128; s > 0; s >>= 1) { if (t < s) sh[t] = fmaxf(sh[t], sh[t + s]); __syncthreads(); }
    float M = sh[0];
    __syncthreads();
    float e = (t < NC) ? expf(pv - M) : 0.f;
    sh[t] = e;
    __syncthreads();
    for (int s = 128; s > 0; s >>= 1) { if (t < s) sh[t] += sh[t + s]; __syncthreads(); }
    float S = sh[0];
    if (t < NC) g_logp[t] = logf(e / S + 1e-6f);
}

__global__ void prep_comp_kernel(const float* __restrict__ means,
                                 const float* __restrict__ bw) {
    int j = blockIdx.x;
    int t = threadIdx.x;   // 128
    float ld = 0.f, cj = 0.f;
    #pragma unroll
    for (int d = t; d < ND; d += 128) {
        float bv = bw[j * ND + d];
        bv = fminf(fmaxf(bv, 1e-6f), 1000.f);
        float inv = 1.0f / bv;
        float mu  = means[j * ND + d];
        float m2  = -2.0f * mu * inv;
        __nv_bfloat16 h = __float2bfloat16(inv);
        g_Bh[j * K2 + d] = h;
        g_Bl[j * K2 + d] = __float2bfloat16(inv - __bfloat162float(h));
        __nv_bfloat16 h2 = __float2bfloat16(m2);
        g_Bh[j * K2 + ND + d] = h2;
        g_Bl[j * K2 + ND + d] = __float2bfloat16(m2 - __bfloat162float(h2));
        ld += logf(bv);
        cj += mu * mu * inv;
    }
    __shared__ float shd[128], shc[128];
    shd[t] = ld; shc[t] = cj;
    __syncthreads();
    for (int s = 64; s > 0; s >>= 1) {
        if (t < s) { shd[t] += shd[t + s]; shc[t] += shc[t + s]; }
        __syncthreads();
    }
    if (t == 0)
        g_bias[j] = -0.5f * (D_LOG_2PI + shd[0] + shc[0]) + g_logw[j];
}

// ---------------- main GEMM (mma.sync bf16x3) ----------------
__global__ void __launch_bounds__(NTHR, 1) gemm_kernel() {
    extern __shared__ char smem[];
    uint32_t sb = smem_u32(smem);
    int tid = threadIdx.x;
    int wid = tid >> 5, lane = tid & 31;
    int rowBase = blockIdx.y * BM;
    int colBase = blockIdx.x * BN;
    float* bias_sm = (float*)smem;

    if (tid < 128) bias_sm[tid] = g_bias[colBase + tid];

    // warp tile: 16 warps = 4(m) x 4(n); warp tile 64m x 32n
    int wm = (wid & 3) * 64;
    int wn = (wid >> 2) * 32;

    float acc[64];
    #pragma unroll
    for (int i = 0; i < 64; i++) acc[i] = 0.f;

    // ---- stage loader ----
    auto load_stage = [&](int buf, int k0) {
        uint32_t st = sb + 512 + buf * STAGE_BYTES;
        // Ah / Al: 256 rows x 8 chunks of 16B
        #pragma unroll
        for (int it = 0; it < 4; it++) {
            int idx = tid + it * NTHR;           // 0..2047
            int row = idx >> 3, ch = idx & 7;
            uint32_t so = swz((uint32_t)(row * 128 + ch * 16));
            const __nv_bfloat16* ga = g_Ah + (size_t)(rowBase + row) * K2 + k0 + ch * 8;
            const __nv_bfloat16* gl = g_Al + (size_t)(rowBase + row) * K2 + k0 + ch * 8;
            cp16(st + so, ga);
            cp16(st + 32768 + so, gl);
        }
        // Bh / Bl: 128 rows x 8 chunks
        #pragma unroll
        for (int it = 0; it < 2; it++) {
            int idx = tid + it * NTHR;           // 0..1023
            int row = idx >> 3, ch = idx & 7;
            uint32_t so = swz((uint32_t)(row * 128 + ch * 16));
            const __nv_bfloat16* gb = g_Bh + (size_t)(colBase + row) * K2 + k0 + ch * 8;
            const __nv_bfloat16* gl = g_Bl + (size_t)(colBase + row) * K2 + k0 + ch * 8;
            cp16(st + 65536 + so, gb);
            cp16(st + 81920 + so, gl);
        }
    };

    int lrow = lane & 15;
    int lcol = (lane >> 4) * 16;

    load_stage(0, 0);
    asm volatile("cp.async.commit_group;" ::: "memory");

    for (int s = 0; s < NSTEPS; s++) {
        int buf = s & 1;
        if (s + 1 < NSTEPS) {
            load_stage(buf ^ 1, (s + 1) * BK);
            asm volatile("cp.async.commit_group;" ::: "memory");
            asm volatile("cp.async.wait_group 1;" ::: "memory");
        } else {
            asm volatile("cp.async.wait_group 0;" ::: "memory");
        }
        __syncthreads();

        uint32_t stA  = sb + 512 + buf * STAGE_BYTES;
        uint32_t stAl = stA + 32768;
        uint32_t stB  = stA + 65536;
        uint32_t stBl = stA + 81920;

        #pragma unroll
        for (int ks = 0; ks < 4; ks++) {
            int kb = ks * 32 + lcol;   // byte offset within 128B row

            uint32_t ah[4][4], bh[2][4];
            #pragma unroll
            for (int mi = 0; mi < 4; mi++)
                ldsm4(ah[mi], stA + swz((uint32_t)((wm + mi * 16 + lrow) * 128 + kb)));
            #pragma unroll
            for (int nj = 0; nj < 2; nj++)
                ldsm4(bh[nj], stB + swz((uint32_t)((wn + nj * 16 + lrow) * 128 + kb)));

            // Ah * Bh
            #pragma unroll
            for (int mi = 0; mi < 4; mi++)
                #pragma unroll
                for (int n = 0; n < 4; n++) {
                    uint32_t bb[2] = { bh[n >> 1][n & 1], bh[n >> 1][(n & 1) + 2] };
                    mma_bf16(&acc[(mi * 4 + n) * 4], ah[mi], bb);
                }

            // Ah * Bl
            uint32_t bl[2][4];
            #pragma unroll
            for (int nj = 0; nj < 2; nj++)
                ldsm4(bl[nj], stBl + swz((uint32_t)((wn + nj * 16 + lrow) * 128 + kb)));
            #pragma unroll
            for (int mi = 0; mi < 4; mi++)
                #pragma unroll
                for (int n = 0; n < 4; n++) {
                    uint32_t bb[2] = { bl[n >> 1][n & 1], bl[n >> 1][(n & 1) + 2] };
                    mma_bf16(&acc[(mi * 4 + n) * 4], ah[mi], bb);
                }

            // Al * Bh
            uint32_t al[4][4];
            #pragma unroll
            for (int mi = 0; mi < 4; mi++)
                ldsm4(al[mi], stAl + swz((uint32_t)((wm + mi * 16 + lrow) * 128 + kb)));
            #pragma unroll
            for (int mi = 0; mi < 4; mi++)
                #pragma unroll
                for (int n = 0; n < 4; n++) {
                    uint32_t bb[2] = { bh[n >> 1][n & 1], bh[n >> 1][(n & 1) + 2] };
                    mma_bf16(&acc[(mi * 4 + n) * 4], al[mi], bb);
                }
        }
        __syncthreads();
    }

    // ---- epilogue: stage C to smem, fused lse over K=16 ----
    float* csh = (float*)(smem + 512);
    #pragma unroll
    for (int mi = 0; mi < 4; mi++)
        #pragma unroll
        for (int nj = 0; nj < 4; nj++) {
            float* a = &acc[(mi * 4 + nj) * 4];
            int r0 = wm + mi * 16 + (lane >> 2);
            int c0 = wn + nj * 8 + 2 * (lane & 3);
            csh[r0 * CPAD + c0]           = a[0];
            csh[r0 * CPAD + c0 + 1]       = a[1];
            csh[(r0 + 8) * CPAD + c0]     = a[2];
            csh[(r0 + 8) * CPAD + c0 + 1] = a[3];
        }
    __syncthreads();

    #pragma unroll
    for (int i = 0; i < 4; i++) {
        int p = tid + i * NTHR;      // 0..2047: 256 rows x 8 classes
        int row = p >> 3, cl = p & 7;
        const float* base = &csh[row * CPAD + cl * 16];
        float4 x0 = *(const float4*)(base + 0);
        float4 x1 = *(const float4*)(base + 4);
        float4 x2 = *(const float4*)(base + 8);
        float4 x3 = *(const float4*)(base + 12);
        float v[16] = {x0.x, x0.y, x0.z, x0.w, x1.x, x1.y, x1.z, x1.w,
                       x2.x, x2.y, x2.z, x2.w, x3.x, x3.y, x3.z, x3.w};
        #pragma unroll
        for (int j = 0; j < 16; j++)
            v[j] = fmaf(-0.5f, v[j], bias_sm[cl * 16 + j]);
        float m = v[0];
        #pragma unroll
        for (int j = 1; j < 16; j++) m = fmaxf(m, v[j]);
        float sum = 0.f;
        #pragma unroll
        for (int j = 0; j < 16; j++) sum += __expf(v[j] - m);
        g_cls[(size_t)(rowBase + row) * NC + (colBase >> 4) + cl] = m + __logf(sum);
    }
}

// ---------------- per-row reduction over classes ----------------
__global__ void reduce_kernel(float* __restrict__ out) {
    __shared__ float sh[256];
    size_t row = blockIdx.x;
    int t = threadIdx.x;
    float lc = -1e30f;
    if (t < NC) lc = g_cls[row * NC + t] + g_logp[t];
    sh[t] = lc;
    __syncthreads();
    for (int s = 128; s > 0; s >>= 1) { if (t < s) sh[t] = fmaxf(sh[t], sh[t + s]); __syncthreads(); }
    float M = sh[0];
    __syncthreads();
    sh[t] = (t < NC) ? __expf(lc - M) : 0.f;
    __syncthreads();
    for (int s = 128; s > 0; s >>= 1) { if (t < s) sh[t] += sh[t + s]; __syncthreads(); }
    float lse = M + __logf(sh[0]);
    if (t < NC) out[row * NC + t] = lc - lse;
}

// ---------------- launch ----------------
extern "C" void kernel_launch(void* const* d_in, const int* in_sizes, int n_in,
                              void* d_out, int out_size) {
    const float* x       = (const float*)d_in[0];
    const float* means   = (const float*)d_in[1];
    const float* bw      = (const float*)d_in[2];
    const float* weights = (const float*)d_in[3];
    const float* priors  = (const float*)d_in[4];
    float* out = (float*)d_out;

    cudaFuncSetAttribute(gemm_kernel, cudaFuncAttributeMaxDynamicSharedMemorySize, SMEM_TOTAL);

    prep_x_kernel<<<(NB * ND + 255) / 256, 256>>>(x);
    prep_wp_kernel<<<1, 256>>>(weights, priors);
    prep_comp_kernel<<<NCK, 128>>>(means, bw);

    dim3 grid(NCK / BN, NB / BM);   // (25, 32)
    gemm_kernel<<<grid, NTHR, SMEM_TOTAL>>>();

    reduce_kernel<<<NB, 256>>>(out);
}

// round 4
// speedup vs baseline: 2.4459x; 1.0067x over previous
#include <cuda_runtime.h>
#include <cuda_bf16.h>
#include <math.h>
#include <stdint.h>

// Problem constants
#define NB   8192
#define NC   200
#define NK   16
#define ND   512
#define NCK  3200
#define K2   1024          // 2*ND concatenated GEMM K
#define D_LOG_2PI 940.9930579935848f

// GEMM tiling
#define BM 256
#define BN 128
#define BK 64              // bf16 per stage row (128 bytes, SW128 atom)
#define NSTEPS (K2/BK)     // 16
#define NTHR 512

// SMEM layout (dynamic):
//  [0:512)    bias_sm (128 floats)
//  [512 + s*STAGE): stage s: Ah(32K) Al(32K) Bh(16K) Bl(16K)
//  epilogue reuses [512, ...) as C staging (256 x 136 floats)
#define STAGE_BYTES 98304
#define SMEM_TOTAL  (512 + 2 * STAGE_BYTES)
#define CPAD 136

// ---------------- scratch (device globals) ----------------
__device__ __nv_bfloat16 g_Ah[NB * K2];
__device__ __nv_bfloat16 g_Al[NB * K2];
__device__ __nv_bfloat16 g_Bh[NCK * K2];
__device__ __nv_bfloat16 g_Bl[NCK * K2];
__device__ float g_bias[NCK];
__device__ float g_logw[NCK];
__device__ float g_logp[NC];
__device__ float g_cls[NB * NC];

// ---------------- helpers ----------------
__device__ __forceinline__ uint32_t smem_u32(const void* p) {
    uint32_t a;
    asm("{ .reg .u64 t; cvta.to.shared.u64 t, %1; cvt.u32.u64 %0, t; }" : "=r"(a) : "l"(p));
    return a;
}
__device__ __forceinline__ uint32_t swz(uint32_t o) {   // SW128, 128B rows
    return o ^ (((o >> 7) & 7) << 4);
}
__device__ __forceinline__ void cp16(uint32_t saddr, const void* gaddr) {
    asm volatile("cp.async.cg.shared.global [%0], [%1], 16;" :: "r"(saddr), "l"(gaddr));
}
__device__ __forceinline__ void ldsm4(uint32_t* r, uint32_t addr) {
    asm volatile("ldmatrix.sync.aligned.m8n8.x4.shared.b16 {%0,%1,%2,%3}, [%4];"
        : "=r"(r[0]), "=r"(r[1]), "=r"(r[2]), "=r"(r[3]) : "r"(addr));
}
__device__ __forceinline__ void mma_bf16(float* c, const uint32_t* a, const uint32_t* b) {
    asm("mma.sync.aligned.m16n8k16.row.col.f32.bf16.bf16.f32 "
        "{%0,%1,%2,%3}, {%4,%5,%6,%7}, {%8,%9}, {%0,%1,%2,%3};"
        : "+f"(c[0]), "+f"(c[1]), "+f"(c[2]), "+f"(c[3])
        : "r"(a[0]), "r"(a[1]), "r"(a[2]), "r"(a[3]), "r"(b[0]), "r"(b[1]));
}

// ---------------- prep kernels ----------------
__global__ void prep_x_kernel(const float* __restrict__ x) {
    int i = blockIdx.x * blockDim.x + threadIdx.x;
    if (i < NB * ND) {
        int b = i >> 9, d = i & 511;
        float v = x[i];
        float a = v * v;
        __nv_bfloat16 h = __float2bfloat16(a);
        g_Ah[b * K2 + d] = h;
        g_Al[b * K2 + d] = __float2bfloat16(a - __bfloat162float(h));
        __nv_bfloat16 h2 = __float2bfloat16(v);
        g_Ah[b * K2 + ND + d] = h2;
        g_Al[b * K2 + ND + d] = __float2bfloat16(v - __bfloat162float(h2));
    }
}

__global__ void prep_wp_kernel(const float* __restrict__ weights,
                               const float* __restrict__ priors) {
    __shared__ float sh[256];
    int t = threadIdx.x;
    if (t < NC) {
        float wv[NK];
        float m = -1e30f;
        #pragma unroll
        for (int k = 0; k < NK; k++) { wv[k] = weights[t * NK + k]; m = fmaxf(m, wv[k]); }
        float s = 0.f;
        #pragma unroll
        for (int k = 0; k < NK; k++) s += expf(wv[k] - m);
        float inv_s = 1.f / s;
        #pragma unroll
        for (int k = 0; k < NK; k++)
            g_logw[t * NK + k] = logf(expf(wv[k] - m) * inv_s + 1e-6f);
    }
    float pv = (t < NC) ? priors[t] : -1e30f;
    sh[t] = pv;
    __syncthreads();
    for (int s = 128; s > 0; s >>= 1) { if (t < s) sh[t] = fmaxf(sh[t], sh[t + s]); __syncthreads(); }
    float M = sh[0];
    __syncthreads();
    float e = (t < NC) ? expf(pv - M) : 0.f;
    sh[t] = e;
    __syncthreads();
    for (int s = 128; s > 0; s >>= 1) { if (t < s) sh[t] += sh[t + s]; __syncthreads(); }
    float S = sh[0];
    if (t < NC) g_logp[t] = logf(e / S + 1e-6f);
}

__global__ void prep_comp_kernel(const float* __restrict__ means,
                                 const float* __restrict__ bw) {
    int j = blockIdx.x;
    int t = threadIdx.x;   // 128
    float ld = 0.f, cj = 0.f;
    #pragma unroll
    for (int d = t; d < ND; d += 128) {
        float bv = bw[j * ND + d];
        bv = fminf(fmaxf(bv, 1e-6f), 1000.f);
        float inv = 1.0f / bv;
        float mu  = means[j * ND + d];
        float m2  = -2.0f * mu * inv;
        __nv_bfloat16 h = __float2bfloat16(inv);
        g_Bh[j * K2 + d] = h;
        g_Bl[j * K2 + d] = __float2bfloat16(inv - __bfloat162float(h));
        __nv_bfloat16 h2 = __float2bfloat16(m2);
        g_Bh[j * K2 + ND + d] = h2;
        g_Bl[j * K2 + ND + d] = __float2bfloat16(m2 - __bfloat162float(h2));
        ld += logf(bv);
        cj += mu * mu * inv;
    }
    __shared__ float shd[128], shc[128];
    shd[t] = ld; shc[t] = cj;
    __syncthreads();
    for (int s = 64; s > 0; s >>= 1) {
        if (t < s) { shd[t] += shd[t + s]; shc[t] += shc[t + s]; }
        __syncthreads();
    }
    if (t == 0)
        g_bias[j] = -0.5f * (D_LOG_2PI + shd[0] + shc[0]) + g_logw[j];
}

// ---------------- main GEMM (mma.sync bf16x3) ----------------
__global__ void __launch_bounds__(NTHR, 1) gemm_kernel() {
    extern __shared__ char smem[];
    uint32_t sb = smem_u32(smem);
    int tid = threadIdx.x;
    int wid = tid >> 5, lane = tid & 31;
    int rowBase = blockIdx.y * BM;
    int colBase = blockIdx.x * BN;
    float* bias_sm = (float*)smem;

    if (tid < 128) bias_sm[tid] = g_bias[colBase + tid];

    // warp tile: 16 warps = 4(m) x 4(n); warp tile 64m x 32n
    int wm = (wid & 3) * 64;
    int wn = (wid >> 2) * 32;
    int lrow = lane & 15;
    int lcol = (lane >> 4) * 16;   // folded into kb

    // ---- precomputed cp.async offsets (element offsets are < 2^24) ----
    uint32_t gAo[4], sAo[4], gBo[2], sBo[2];
    #pragma unroll
    for (int it = 0; it < 4; it++) {
        int idx = tid + it * NTHR;          // 0..2047
        int row = idx >> 3, ch = idx & 7;
        gAo[it] = (uint32_t)((rowBase + row) * K2 + ch * 8);
        sAo[it] = swz((uint32_t)(row * 128 + ch * 16));
    }
    #pragma unroll
    for (int it = 0; it < 2; it++) {
        int idx = tid + it * NTHR;          // 0..1023
        int row = idx >> 3, ch = idx & 7;
        gBo[it] = (uint32_t)((colBase + row) * K2 + ch * 8);
        sBo[it] = swz((uint32_t)(row * 128 + ch * 16));
    }

    // ---- precomputed ldmatrix base addresses (swizzle at kb=0); addr = base ^ kb ----
    uint32_t baseA[4], baseB[2];
    #pragma unroll
    for (int mi = 0; mi < 4; mi++) {
        int r = wm + mi * 16 + lrow;
        baseA[mi] = sb + 512 + (uint32_t)(r * 128 + ((r & 7) << 4));
    }
    #pragma unroll
    for (int nj = 0; nj < 2; nj++) {
        int r = wn + nj * 16 + lrow;
        baseB[nj] = sb + 512 + 65536 + (uint32_t)(r * 128 + ((r & 7) << 4));
    }

    float acc[64];
    #pragma unroll
    for (int i = 0; i < 64; i++) acc[i] = 0.f;

    auto load_stage = [&](int buf, int k0) {
        uint32_t st = sb + 512 + buf * STAGE_BYTES;
        #pragma unroll
        for (int it = 0; it < 4; it++) {
            cp16(st + sAo[it],         g_Ah + gAo[it] + k0);
            cp16(st + 32768 + sAo[it], g_Al + gAo[it] + k0);
        }
        #pragma unroll
        for (int it = 0; it < 2; it++) {
            cp16(st + 65536 + sBo[it], g_Bh + gBo[it] + k0);
            cp16(st + 81920 + sBo[it], g_Bl + gBo[it] + k0);
        }
    };

    load_stage(0, 0);
    asm volatile("cp.async.commit_group;" ::: "memory");

    for (int s = 0; s < NSTEPS; s++) {
        int buf = s & 1;
        uint32_t bo = buf * STAGE_BYTES;

        asm volatile("cp.async.wait_group 0;" ::: "memory");
        __syncthreads();                        // single barrier per iteration

        if (s + 1 < NSTEPS) {
            load_stage(buf ^ 1, (s + 1) * BK);
            asm volatile("cp.async.commit_group;" ::: "memory");
        }

        uint32_t aA[4], aB[2];
        #pragma unroll
        for (int mi = 0; mi < 4; mi++) aA[mi] = baseA[mi] + bo;
        #pragma unroll
        for (int nj = 0; nj < 2; nj++) aB[nj] = baseB[nj] + bo;

        #pragma unroll
        for (int ks = 0; ks < 4; ks++) {
            uint32_t kb = (uint32_t)(ks * 32 + lcol);

            uint32_t ah[4][4], bh[2][4], bl[2][4];
            #pragma unroll
            for (int mi = 0; mi < 4; mi++) ldsm4(ah[mi], aA[mi] ^ kb);
            #pragma unroll
            for (int nj = 0; nj < 2; nj++) ldsm4(bh[nj], aB[nj] ^ kb);
            #pragma unroll
            for (int nj = 0; nj < 2; nj++) ldsm4(bl[nj], (aB[nj] + 16384u) ^ kb);

            // Ah * Bh
            #pragma unroll
            for (int mi = 0; mi < 4; mi++)
                #pragma unroll
                for (int n = 0; n < 4; n++) {
                    uint32_t bb[2] = { bh[n >> 1][n & 1], bh[n >> 1][(n & 1) + 2] };
                    mma_bf16(&acc[(mi * 4 + n) * 4], ah[mi], bb);
                }
            // Ah * Bl
            #pragma unroll
            for (int mi = 0; mi < 4; mi++)
                #pragma unroll
                for (int n = 0; n < 4; n++) {
                    uint32_t bb[2] = { bl[n >> 1][n & 1], bl[n >> 1][(n & 1) + 2] };
                    mma_bf16(&acc[(mi * 4 + n) * 4], ah[mi], bb);
                }
            // Al * Bh (load Al late so its regs overlap the Ah lifetime minimally)
            uint32_t al[4][4];
            #pragma unroll
            for (int mi = 0; mi < 4; mi++) ldsm4(al[mi], (aA[mi] + 32768u) ^ kb);
            #pragma unroll
            for (int mi = 0; mi < 4; mi++)
                #pragma unroll
                for (int n = 0; n < 4; n++) {
                    uint32_t bb[2] = { bh[n >> 1][n & 1], bh[n >> 1][(n & 1) + 2] };
                    mma_bf16(&acc[(mi * 4 + n) * 4], al[mi], bb);
                }
        }
    }
    __syncthreads();    // all ldsm done before reusing smem as C staging

    // ---- epilogue: stage C to smem, fused lse over K=16 ----
    float* csh = (float*)(smem + 512);
    #pragma unroll
    for (int mi = 0; mi < 4; mi++)
        #pragma unroll
        for (int nj = 0; nj < 4; nj++) {
            float* a = &acc[(mi * 4 + nj) * 4];
            int r0 = wm + mi * 16 + (lane >> 2);
            int c0 = wn + nj * 8 + 2 * (lane & 3);
            csh[r0 * CPAD + c0]           = a[0];
            csh[r0 * CPAD + c0 + 1]       = a[1];
            csh[(r0 + 8) * CPAD + c0]     = a[2];
            csh[(r0 + 8) * CPAD + c0 + 1] = a[3];
        }
    __syncthreads();

    #pragma unroll
    for (int i = 0; i < 4; i++) {
        int p = tid + i * NTHR;      // 0..2047: 256 rows x 8 classes
        int row = p >> 3, cl = p & 7;
        const float* base = &csh[row * CPAD + cl * 16];
        float4 x0 = *(const float4*)(base + 0);
        float4 x1 = *(const float4*)(base + 4);
        float4 x2 = *(const float4*)(base + 8);
        float4 x3 = *(const float4*)(base + 12);
        float v[16] = {x0.x, x0.y, x0.z, x0.w, x1.x, x1.y, x1.z, x1.w,
                       x2.x, x2.y, x2.z, x2.w, x3.x, x3.y, x3.z, x3.w};
        #pragma unroll
        for (int j = 0; j < 16; j++)
            v[j] = fmaf(-0.5f, v[j], bias_sm[cl * 16 + j]);
        float m = v[0];
        #pragma unroll
        for (int j = 1; j < 16; j++) m = fmaxf(m, v[j]);
        float sum = 0.f;
        #pragma unroll
        for (int j = 0; j < 16; j++) sum += __expf(v[j] - m);
        g_cls[(size_t)(rowBase + row) * NC + (colBase >> 4) + cl] = m + __logf(sum);
    }
}

// ---------------- per-row reduction over classes ----------------
__global__ void reduce_kernel(float* __restrict__ out) {
    __shared__ float sh[256];
    size_t row = blockIdx.x;
    int t = threadIdx.x;
    float lc = -1e30f;
    if (t < NC) lc = g_cls[row * NC + t] + g_logp[t];
    sh[t] = lc;
    __syncthreads();
    for (int s = 128; s > 0; s >>= 1) { if (t < s) sh[t] = fmaxf(sh[t], sh[t + s]); __syncthreads(); }
    float M = sh[0];
    __syncthreads();
    sh[t] = (t < NC) ? __expf(lc - M) : 0.f;
    __syncthreads();
    for (int s = 128; s > 0; s >>= 1) { if (t < s) sh[t] += sh[t + s]; __syncthreads(); }
    float lse = M + __logf(sh[0]);
    if (t < NC) out[row * NC + t] = lc - lse;
}

// ---------------- launch ----------------
extern "C" void kernel_launch(void* const* d_in, const int* in_sizes, int n_in,
                              void* d_out, int out_size) {
    const float* x       = (const float*)d_in[0];
    const float* means   = (const float*)d_in[1];
    const float* bw      = (const float*)d_in[2];
    const float* weights = (const float*)d_in[3];
    const float* priors  = (const float*)d_in[4];
    float* out = (float*)d_out;

    cudaFuncSetAttribute(gemm_kernel, cudaFuncAttributeMaxDynamicSharedMemorySize, SMEM_TOTAL);

    prep_x_kernel<<<(NB * ND + 255) / 256, 256>>>(x);
    prep_wp_kernel<<<1, 256>>>(weights, priors);
    prep_comp_kernel<<<NCK, 128>>>(means, bw);

    dim3 grid(NCK / BN, NB / BM);   // (25, 32)
    gemm_kernel<<<grid, NTHR, SMEM_TOTAL>>>();

    reduce_kernel<<<NB, 256>>>(out);
}